// round 1
// baseline (speedup 1.0000x reference)
#include <cuda_runtime.h>

#define BATCH 4
#define CIN   96
#define DI    192
#define HH    128
#define WW    128
#define HWSZ  16384
#define KDIR  4
#define RANK  6

// ---------------- scratch (static device globals; no runtime alloc) ----------------
__device__ float g_t1[(size_t)BATCH*DI*HWSZ];                 // in_proj output (B,D,HW)
__device__ float g_xf[(size_t)BATCH*DI*HWSZ];                 // conv+silu output (B,D,HW)
__device__ float g_xdbl[(size_t)BATCH*KDIR*HWSZ*8];           // (B,K,L,8) in scan order
__device__ float g_xs[(size_t)BATCH*KDIR*HWSZ*DI];            // (B,K,L,D) in scan order
__device__ float g_ys[(size_t)BATCH*KDIR*HWSZ*DI];            // (B,K,L,D) scan result

// =====================================================================
// K1: in_proj  t1[b,o,pos] = sum_c w[o,c] * x[b,c,pos]
// grid (HW/64, B), block 256, dyn smem = 96*196*4 + 96*68*4
// =====================================================================
__global__ void k1_inproj(const float* __restrict__ x, const float* __restrict__ w) {
    extern __shared__ float sm1[];
    float* sw = sm1;              // transposed: sw[c*196 + o]
    float* sx = sm1 + 96*196;     // sx[c*68 + t]
    int b = blockIdx.y;
    int pos0 = blockIdx.x * 64;
    int tid = threadIdx.x;

    for (int i = tid; i < DI*CIN; i += 256) {
        int o = i / CIN, c = i % CIN;
        sw[c*196 + o] = w[i];
    }
    for (int i = tid; i < CIN*64; i += 256) {
        int c = i >> 6, t = i & 63;
        sx[c*68 + t] = x[((size_t)b*CIN + c)*HWSZ + pos0 + t];
    }
    __syncthreads();

    int tg = tid & 15, og = tid >> 4;   // 16 token-groups x 16 o-groups
    int t0 = tg * 4, o0 = og * 12;
    float acc[12][4];
    #pragma unroll
    for (int i = 0; i < 12; i++)
        #pragma unroll
        for (int j = 0; j < 4; j++) acc[i][j] = 0.f;

    for (int c = 0; c < CIN; ++c) {
        float4 xv = *(const float4*)&sx[c*68 + t0];
        float xa[4] = {xv.x, xv.y, xv.z, xv.w};
        const float* wrow = &sw[c*196 + o0];
        #pragma unroll
        for (int i = 0; i < 3; ++i) {
            float4 wv = *(const float4*)&wrow[i*4];
            float wa[4] = {wv.x, wv.y, wv.z, wv.w};
            #pragma unroll
            for (int oi = 0; oi < 4; ++oi)
                #pragma unroll
                for (int tj = 0; tj < 4; ++tj)
                    acc[i*4+oi][tj] += wa[oi] * xa[tj];
        }
    }
    #pragma unroll
    for (int i = 0; i < 12; ++i) {
        float4 v = make_float4(acc[i][0], acc[i][1], acc[i][2], acc[i][3]);
        *(float4*)&g_t1[((size_t)b*DI + o0 + i)*HWSZ + pos0 + t0] = v;
    }
}

// =====================================================================
// K2: depthwise 3x3 conv (SAME, zero pad) + bias + silu
// grid (HH/8, DI, B), block 256
// =====================================================================
__global__ void k2_conv(const float* __restrict__ cw, const float* __restrict__ cb) {
    __shared__ float s[10][128];
    int b = blockIdx.z, d = blockIdx.y, h0 = blockIdx.x * 8;
    int tid = threadIdx.x;
    const float* src = g_t1 + ((size_t)b*DI + d)*HWSZ;

    for (int i = tid; i < 10*128; i += 256) {
        int r = i >> 7, c = i & 127;
        int h = h0 + r - 1;
        s[r][c] = (h >= 0 && h < HH) ? src[h*WW + c] : 0.f;
    }
    float w9[9];
    #pragma unroll
    for (int i = 0; i < 9; i++) w9[i] = cw[d*9 + i];
    float bias = cb[d];
    __syncthreads();

    #pragma unroll
    for (int q = 0; q < 4; q++) {
        int idx = tid + q*256;
        int r = idx >> 7, c = idx & 127;
        float sum = bias;
        #pragma unroll
        for (int dr = 0; dr < 3; dr++) {
            #pragma unroll
            for (int dc = 0; dc < 3; dc++) {
                int cc = c + dc - 1;
                float v = (cc >= 0 && cc < WW) ? s[r+dr][cc] : 0.f;
                sum += w9[dr*3+dc] * v;
            }
        }
        float o = sum / (1.f + __expf(-sum));   // silu
        g_xf[((size_t)b*DI + d)*HWSZ + (h0 + r)*WW + c] = o;
    }
}

// =====================================================================
// K3: x_proj (8 outputs per token per direction) + scatter to scan order,
//     AND scatter xs rows (d-contiguous) to scan order.
// grid (HW/64, B), block 256, dyn smem = 192*68*4 + 192*33*4
// =====================================================================
__global__ void k3_proj_gather(const float* __restrict__ xpw, const int* __restrict__ inv) {
    extern __shared__ float sm3[];
    float* sxf = sm3;             // [d*68 + t]
    float* sw  = sm3 + DI*68;     // [d*33 + kc], kc = k*8+c
    int b = blockIdx.y, pos0 = blockIdx.x * 64, tid = threadIdx.x;

    for (int i = tid; i < DI*64; i += 256) {
        int d = i >> 6, t = i & 63;
        sxf[d*68 + t] = g_xf[((size_t)b*DI + d)*HWSZ + pos0 + t];
    }
    for (int i = tid; i < 32*DI; i += 256) {
        int kc = i / DI, d = i % DI;
        sw[d*33 + kc] = xpw[i];
    }
    __syncthreads();

    // ---- phase A: x_dbl (32 outputs per token), scatter to scan order ----
    int tg = tid & 15, kg = tid >> 4;   // 16 tok-grp x 16 kc-grp(2 each)
    int t0 = tg * 4, kc0 = kg * 2;
    float acc[4][2] = {{0,0},{0,0},{0,0},{0,0}};
    for (int d = 0; d < DI; ++d) {
        float4 xv = *(const float4*)&sxf[d*68 + t0];
        float w0 = sw[d*33 + kc0], w1 = sw[d*33 + kc0 + 1];
        acc[0][0] += xv.x*w0; acc[0][1] += xv.x*w1;
        acc[1][0] += xv.y*w0; acc[1][1] += xv.y*w1;
        acc[2][0] += xv.z*w0; acc[2][1] += xv.z*w1;
        acc[3][0] += xv.w*w0; acc[3][1] += xv.w*w1;
    }
    int k = kc0 >> 3, c = kc0 & 7;
    #pragma unroll
    for (int j = 0; j < 4; ++j) {
        int pos = pos0 + t0 + j;
        int l = inv[k*HWSZ + pos];
        float2 v = make_float2(acc[j][0], acc[j][1]);
        *(float2*)&g_xdbl[(((size_t)(b*KDIR + k)*HWSZ + l) << 3) + c] = v;
    }

    // ---- phase B: scatter xs rows (768B each) to scan order ----
    int lane = tid & 31, wid = tid >> 5;   // 8 warps, 32 rows each
    for (int rr = 0; rr < 32; ++rr) {
        int row = wid*32 + rr;             // 0..255 = (k, pos-offset)
        int kk = row >> 6, po = row & 63;
        int pos = pos0 + po;
        int l = inv[kk*HWSZ + pos];
        float* dst = &g_xs[((size_t)(b*KDIR + kk)*HWSZ + l)*DI];
        #pragma unroll
        for (int i = 0; i < 6; ++i)
            dst[lane + 32*i] = sxf[(lane + 32*i)*68 + po];
    }
}

// =====================================================================
// K4: selective scan. block = (b, k, 16-d tile); 512 thr = 32 slots x 16 d.
// Chunk of 256 l's: thread scans 8 locally, warp w does the 32-slot scan
// for d = w (carry h kept in warp registers).
// grid (12, K, B), block 512
// =====================================================================
__global__ void __launch_bounds__(512) k4_scan(const float* __restrict__ dtw,
                        const float* __restrict__ dtb,
                        const float* __restrict__ Alog,
                        const float* __restrict__ Dsv) {
    __shared__ float s_pa[32*17], s_pb[32*17], s_hs[32*17];
    int b = blockIdx.z, k = blockIdx.y, dg = blockIdx.x;
    int tid = threadIdx.x;
    int dsub = tid & 15, slot = tid >> 4;
    int d = dg*16 + dsub;
    int kd = k*DI + d;
    int lane = tid & 31, wid = tid >> 5;   // 16 warps; warp w owns scan of d=dg*16+w

    float w0 = dtw[kd*6+0], w1 = dtw[kd*6+1], w2 = dtw[kd*6+2];
    float w3 = dtw[kd*6+3], w4 = dtw[kd*6+4], w5 = dtw[kd*6+5];
    float bias = dtb[kd];
    float Aval = -__expf(Alog[kd]);
    float Dval = Dsv[kd];
    size_t base_bk = (size_t)(b*KDIR + k)*HWSZ;
    float hprev = 0.f;   // uniform per warp (scan-role state)

    for (int ch = 0; ch < 64; ++ch) {
        int l0 = ch*256 + slot*8;
        float a[8], bu[8], Cv[8], du[8];
        #pragma unroll
        for (int j = 0; j < 8; ++j) {
            int l = l0 + j;
            const float4* xb = (const float4*)&g_xdbl[(base_bk + l) << 3];
            float4 q1 = xb[0];
            float4 q2 = xb[1];
            float u = g_xs[(base_bk + l)*DI + d];
            float dt = bias + w0*q1.x + w1*q1.y + w2*q1.z + w3*q1.w + w4*q2.x + w5*q2.y;
            float delta = fmaxf(dt, 0.f) + __logf(1.f + __expf(-fabsf(dt)));
            a[j]  = __expf(delta * Aval);
            bu[j] = delta * q2.z * u;
            Cv[j] = q2.w;
            du[j] = Dval * u;
        }
        // thread-local combine over 8
        float aP = a[0], bP = bu[0];
        #pragma unroll
        for (int j = 1; j < 8; ++j) { bP = a[j]*bP + bu[j]; aP *= a[j]; }
        s_pa[slot*17 + dsub] = aP;
        s_pb[slot*17 + dsub] = bP;
        __syncthreads();

        // warp `wid` scans the 32 slot-partials of d-index = wid
        {
            float ai = s_pa[lane*17 + wid];
            float bi = s_pb[lane*17 + wid];
            #pragma unroll
            for (int off = 1; off < 32; off <<= 1) {
                float pa = __shfl_up_sync(0xffffffffu, ai, off);
                float pb = __shfl_up_sync(0xffffffffu, bi, off);
                if (lane >= off) { bi = ai*pb + bi; ai *= pa; }
            }
            float aE = __shfl_up_sync(0xffffffffu, ai, 1);
            float bE = __shfl_up_sync(0xffffffffu, bi, 1);
            if (lane == 0) { aE = 1.f; bE = 0.f; }
            s_hs[lane*17 + wid] = aE*hprev + bE;   // h value at slot start
            float aI = __shfl_sync(0xffffffffu, ai, 31);
            float bI = __shfl_sync(0xffffffffu, bi, 31);
            hprev = aI*hprev + bI;                 // carry to next chunk
        }
        __syncthreads();

        float h = s_hs[slot*17 + dsub];
        #pragma unroll
        for (int j = 0; j < 8; ++j) {
            h = a[j]*h + bu[j];
            g_ys[(base_bk + (l0 + j))*DI + d] = Cv[j]*h + du[j];
        }
    }
}

// =====================================================================
// K5: inverse gather + sum over K + gelu(tanh) + out_proj (96x192 matvec)
// grid (HW/64, B), block 256, dyn smem = 192*98*4 + 192*68*4
// =====================================================================
__global__ void k5_out(const float* __restrict__ ow, const int* __restrict__ inv,
                       float* __restrict__ out) {
    extern __shared__ float sm5[];
    float* sw = sm5;              // transposed: sw[d*98 + o]
    float* sg = sm5 + DI*98;      // sg[d*68 + t]
    int b = blockIdx.y, pos0 = blockIdx.x * 64, tid = threadIdx.x;

    for (int i = tid; i < CIN*DI; i += 256) {
        int o = i / DI, d = i % DI;
        sw[d*98 + o] = ow[i];
    }
    // phase 1: gather rows, sum over k, gelu
    int lane = tid & 31, wid = tid >> 5;   // 8 warps x 8 pos each
    #pragma unroll
    for (int pp = 0; pp < 8; ++pp) {
        int po = wid*8 + pp;
        int pos = pos0 + po;
        float acc[6] = {0,0,0,0,0,0};
        #pragma unroll
        for (int kk = 0; kk < KDIR; ++kk) {
            int l = inv[kk*HWSZ + pos];
            const float* src = &g_ys[((size_t)(b*KDIR + kk)*HWSZ + l)*DI];
            #pragma unroll
            for (int i = 0; i < 6; ++i) acc[i] += src[lane + 32*i];
        }
        #pragma unroll
        for (int i = 0; i < 6; ++i) {
            float v = acc[i];
            float z = 0.7978845608f * (v + 0.044715f*v*v*v);
            float t = 2.f / (1.f + __expf(-2.f*z)) - 1.f;   // tanh(z)
            sg[(lane + 32*i)*68 + po] = 0.5f * v * (1.f + t);
        }
    }
    __syncthreads();

    // phase 2: out[o] = sum_d w[o,d]*g[d]
    int tg = tid & 15, og = tid >> 4;   // 16 tok-grp(4) x 16 o-grp(6)
    int t0 = tg*4, o0 = og*6;
    float acc2[6][4];
    #pragma unroll
    for (int i = 0; i < 6; i++)
        #pragma unroll
        for (int j = 0; j < 4; j++) acc2[i][j] = 0.f;

    for (int d = 0; d < DI; ++d) {
        float4 gv = *(const float4*)&sg[d*68 + t0];
        float ga[4] = {gv.x, gv.y, gv.z, gv.w};
        const float* wrow = &sw[d*98 + o0];
        #pragma unroll
        for (int i = 0; i < 3; ++i) {
            float2 wv = *(const float2*)&wrow[i*2];
            float wa[2] = {wv.x, wv.y};
            #pragma unroll
            for (int oi = 0; oi < 2; ++oi)
                #pragma unroll
                for (int tj = 0; tj < 4; ++tj)
                    acc2[i*2+oi][tj] += wa[oi] * ga[tj];
        }
    }
    #pragma unroll
    for (int i = 0; i < 6; ++i) {
        float4 v = make_float4(acc2[i][0], acc2[i][1], acc2[i][2], acc2[i][3]);
        *(float4*)&out[((size_t)b*CIN + o0 + i)*HWSZ + pos0 + t0] = v;
    }
}

// =====================================================================
extern "C" void kernel_launch(void* const* d_in, const int* in_sizes, int n_in,
                              void* d_out, int out_size) {
    const float* x    = (const float*)d_in[0];
    // d_in[1] = scan_ids (unused: everything works off inverse_ids)
    const int*   inv  = (const int*)d_in[2];
    const float* ipw  = (const float*)d_in[3];
    const float* cw   = (const float*)d_in[4];
    const float* cb   = (const float*)d_in[5];
    const float* xpw  = (const float*)d_in[6];
    const float* dtw  = (const float*)d_in[7];
    const float* dtb  = (const float*)d_in[8];
    const float* Alog = (const float*)d_in[9];
    const float* Dsv  = (const float*)d_in[10];
    const float* ow   = (const float*)d_in[11];
    float* out = (float*)d_out;

    const int SM1 = (96*196 + 96*68) * 4;
    const int SM3 = (DI*68 + DI*33) * 4;
    const int SM5 = (DI*98 + DI*68) * 4;
    cudaFuncSetAttribute(k1_inproj,      cudaFuncAttributeMaxDynamicSharedMemorySize, SM1);
    cudaFuncSetAttribute(k3_proj_gather, cudaFuncAttributeMaxDynamicSharedMemorySize, SM3);
    cudaFuncSetAttribute(k5_out,         cudaFuncAttributeMaxDynamicSharedMemorySize, SM5);

    dim3 g1(HWSZ/64, BATCH);
    k1_inproj<<<g1, 256, SM1>>>(x, ipw);
    dim3 g2(HH/8, DI, BATCH);
    k2_conv<<<g2, 256>>>(cw, cb);
    dim3 g3(HWSZ/64, BATCH);
    k3_proj_gather<<<g3, 256, SM3>>>(xpw, inv);
    dim3 g4(DI/16, KDIR, BATCH);
    k4_scan<<<g4, 512>>>(dtw, dtb, Alog, Dsv);
    dim3 g5(HWSZ/64, BATCH);
    k5_out<<<g5, 256, SM5>>>(ow, inv, out);
}

// round 2
// speedup vs baseline: 1.1814x; 1.1814x over previous
#include <cuda_runtime.h>

#define BATCH 4
#define CIN   96
#define DI    192
#define HH    128
#define WW    128
#define HWSZ  16384
#define KDIR  4

// ---------------- scratch (static device globals; no runtime alloc) ----------------
__device__ float g_t1[(size_t)BATCH*DI*HWSZ];                 // in_proj output (B,D,HW)
__device__ float g_xf[(size_t)BATCH*DI*HWSZ];                 // conv+silu output (B,D,HW)
__device__ float g_xft[(size_t)BATCH*HWSZ*DI];                // transposed (B,HW,D) d-contiguous
__device__ float g_xdbl[(size_t)BATCH*HWSZ*32];               // (B,HW,K*8) spatial order
__device__ float g_ys[(size_t)BATCH*HWSZ*KDIR*DI];            // (B,HW,K,D) spatial order

// ---------------- f32x2 packed helpers ----------------
__device__ __forceinline__ unsigned long long pk2(float x, float y) {
    unsigned long long r;
    asm("mov.b64 %0, {%1, %2};" : "=l"(r) : "f"(x), "f"(y));
    return r;
}
__device__ __forceinline__ void upk2(float& lo, float& hi, unsigned long long v) {
    asm("mov.b64 {%0, %1}, %2;" : "=f"(lo), "=f"(hi) : "l"(v));
}
#define FMA2(d, a, b) asm("fma.rn.f32x2 %0, %1, %2, %0;" : "+l"(d) : "l"(a), "l"(b))

// =====================================================================
// K1: in_proj  t1[b,o,pos] = sum_c w[o,c] * x[b,c,pos]
// grid (HW/64, B), block 256.  Thread: 12 o (6 o-pairs) x 4 tokens, f32x2.
// smem = W transposed [c][194] + X tile [c][68]  (~100.6KB, 2 blocks/SM)
// =====================================================================
__global__ void __launch_bounds__(256) k1_inproj(const float* __restrict__ x,
                                                 const float* __restrict__ w) {
    extern __shared__ float sm1[];
    float* sw = sm1;              // sw[c*194 + o]
    float* sx = sm1 + 96*194;     // sx[c*68 + t]
    int b = blockIdx.y;
    int pos0 = blockIdx.x * 64;
    int tid = threadIdx.x;

    for (int i = tid; i < DI*CIN; i += 256) {
        int o = i / CIN, c = i % CIN;
        sw[c*194 + o] = w[i];
    }
    for (int i = tid; i < CIN*64; i += 256) {
        int c = i >> 6, t = i & 63;
        sx[c*68 + t] = x[((size_t)b*CIN + c)*HWSZ + pos0 + t];
    }
    __syncthreads();

    int tg = tid & 15, og = tid >> 4;
    int t0 = tg * 4, o0 = og * 12;
    unsigned long long acc[6][4];
    #pragma unroll
    for (int i = 0; i < 6; i++)
        #pragma unroll
        for (int j = 0; j < 4; j++) acc[i][j] = 0ull;

    for (int c = 0; c < CIN; ++c) {
        float4 xv = *(const float4*)&sx[c*68 + t0];
        unsigned long long xp[4] = {pk2(xv.x, xv.x), pk2(xv.y, xv.y),
                                    pk2(xv.z, xv.z), pk2(xv.w, xv.w)};
        const float* wrow = &sw[c*194 + o0];
        #pragma unroll
        for (int i = 0; i < 6; ++i) {
            unsigned long long wp = *(const unsigned long long*)&wrow[2*i];
            #pragma unroll
            for (int t = 0; t < 4; ++t) FMA2(acc[i][t], wp, xp[t]);
        }
    }
    #pragma unroll
    for (int i = 0; i < 6; ++i) {
        float lo[4], hi[4];
        #pragma unroll
        for (int t = 0; t < 4; ++t) upk2(lo[t], hi[t], acc[i][t]);
        size_t r0 = ((size_t)b*DI + o0 + 2*i)*HWSZ + pos0 + t0;
        *(float4*)&g_t1[r0]        = make_float4(lo[0], lo[1], lo[2], lo[3]);
        *(float4*)&g_t1[r0 + HWSZ] = make_float4(hi[0], hi[1], hi[2], hi[3]);
    }
}

// =====================================================================
// K2: depthwise 3x3 conv (SAME) + bias + silu.  grid (HH/8, DI, B), block 256
// =====================================================================
__global__ void k2_conv(const float* __restrict__ cw, const float* __restrict__ cb) {
    __shared__ float s[10][128];
    int b = blockIdx.z, d = blockIdx.y, h0 = blockIdx.x * 8;
    int tid = threadIdx.x;
    const float* src = g_t1 + ((size_t)b*DI + d)*HWSZ;

    for (int i = tid; i < 10*128; i += 256) {
        int r = i >> 7, c = i & 127;
        int h = h0 + r - 1;
        s[r][c] = (h >= 0 && h < HH) ? src[h*WW + c] : 0.f;
    }
    float w9[9];
    #pragma unroll
    for (int i = 0; i < 9; i++) w9[i] = cw[d*9 + i];
    float bias = cb[d];
    __syncthreads();

    #pragma unroll
    for (int q = 0; q < 4; q++) {
        int idx = tid + q*256;
        int r = idx >> 7, c = idx & 127;
        float sum = bias;
        #pragma unroll
        for (int dr = 0; dr < 3; dr++)
            #pragma unroll
            for (int dc = 0; dc < 3; dc++) {
                int cc = c + dc - 1;
                float v = (cc >= 0 && cc < WW) ? s[r+dr][cc] : 0.f;
                sum += w9[dr*3+dc] * v;
            }
        float o = sum / (1.f + __expf(-sum));
        g_xf[((size_t)b*DI + d)*HWSZ + (h0 + r)*WW + c] = o;
    }
}

// =====================================================================
// K3: x_proj (32 outputs per token, spatial order) + write transposed xft.
// No scatter — everything sequential.  grid (HW/64, B), block 256
// =====================================================================
__global__ void k3_proj_tr(const float* __restrict__ xpw) {
    extern __shared__ float sm3[];
    float* sxf = sm3;             // [d*68 + t]
    float* sw  = sm3 + DI*68;     // [d*33 + kc]
    int b = blockIdx.y, pos0 = blockIdx.x * 64, tid = threadIdx.x;

    for (int i = tid; i < DI*64; i += 256) {
        int d = i >> 6, t = i & 63;
        sxf[d*68 + t] = g_xf[((size_t)b*DI + d)*HWSZ + pos0 + t];
    }
    for (int i = tid; i < 32*DI; i += 256) {
        int kc = i / DI, d = i % DI;
        sw[d*33 + kc] = xpw[i];
    }
    __syncthreads();

    // ---- phase A: x_dbl (32 outputs per token), spatial order ----
    int tg = tid & 15, kg = tid >> 4;
    int t0 = tg * 4, kc0 = kg * 2;
    float acc[4][2] = {{0,0},{0,0},{0,0},{0,0}};
    for (int d = 0; d < DI; ++d) {
        float4 xv = *(const float4*)&sxf[d*68 + t0];
        float w0 = sw[d*33 + kc0], w1 = sw[d*33 + kc0 + 1];
        acc[0][0] += xv.x*w0; acc[0][1] += xv.x*w1;
        acc[1][0] += xv.y*w0; acc[1][1] += xv.y*w1;
        acc[2][0] += xv.z*w0; acc[2][1] += xv.z*w1;
        acc[3][0] += xv.w*w0; acc[3][1] += xv.w*w1;
    }
    #pragma unroll
    for (int j = 0; j < 4; ++j) {
        size_t pos = (size_t)pos0 + t0 + j;
        *(float2*)&g_xdbl[((size_t)b*HWSZ + pos)*32 + kc0] = make_float2(acc[j][0], acc[j][1]);
    }

    // ---- phase B: transposed xft write, fully coalesced 768B rows ----
    int lane = tid & 31, wid = tid >> 5;
    #pragma unroll
    for (int pp = 0; pp < 8; ++pp) {
        int po = wid*8 + pp;
        float* dst = &g_xft[((size_t)b*HWSZ + pos0 + po)*DI];
        #pragma unroll
        for (int i = 0; i < 6; ++i)
            dst[lane + 32*i] = sxf[(lane + 32*i)*68 + po];
    }
}

// =====================================================================
// K4: selective scan with direct gathers (xft + xdbl via scan_ids).
// block 256 = 32 slots x 8 d; warp w scans channel d=w via shfl.
// grid (DI/8=24, K, B) = 384 blocks; 4 blocks/SM.
// =====================================================================
__global__ void __launch_bounds__(256, 4) k4_scan(const float* __restrict__ dtw,
                        const float* __restrict__ dtb,
                        const float* __restrict__ Alog,
                        const float* __restrict__ Dsv,
                        const int*   __restrict__ scan) {
    __shared__ float s_pa[32*9], s_pb[32*9], s_hs[32*9];
    int b = blockIdx.z, k = blockIdx.y, dg = blockIdx.x;
    int tid = threadIdx.x;
    int dsub = tid & 7, slot = tid >> 3;
    int d = dg*8 + dsub;
    int kd = k*DI + d;
    int lane = tid & 31, wid = tid >> 5;   // 8 warps; warp w scans d=dg*8+w

    float w0 = dtw[kd*6+0], w1 = dtw[kd*6+1], w2 = dtw[kd*6+2];
    float w3 = dtw[kd*6+3], w4 = dtw[kd*6+4], w5 = dtw[kd*6+5];
    float bias = dtb[kd];
    float Aval = -__expf(Alog[kd]);
    float Dval = Dsv[kd];
    const int*   sc     = scan + k*HWSZ;
    const float* xdbl_b = g_xdbl + (size_t)b*HWSZ*32 + k*8;
    const float* xft_b  = g_xft  + (size_t)b*HWSZ*DI + d;
    float*       ys_b   = g_ys   + (size_t)b*HWSZ*(KDIR*DI) + k*DI + d;
    float hprev = 0.f;

    for (int ch = 0; ch < 64; ++ch) {
        int l0 = ch*256 + slot*8;
        int pos[8];
        #pragma unroll
        for (int j = 0; j < 8; ++j) pos[j] = sc[l0 + j];

        float a[8], bu[8], Cv[8], du[8];
        #pragma unroll
        for (int j = 0; j < 8; ++j) {
            const float4* xb = (const float4*)(xdbl_b + (size_t)pos[j]*32);
            float4 q1 = xb[0];
            float4 q2 = xb[1];
            float u = xft_b[(size_t)pos[j]*DI];
            float dt = bias + w0*q1.x + w1*q1.y + w2*q1.z + w3*q1.w + w4*q2.x + w5*q2.y;
            float delta = fmaxf(dt, 0.f) + __logf(1.f + __expf(-fabsf(dt)));
            a[j]  = __expf(delta * Aval);
            bu[j] = delta * q2.z * u;
            Cv[j] = q2.w;
            du[j] = Dval * u;
        }
        float aP = a[0], bP = bu[0];
        #pragma unroll
        for (int j = 1; j < 8; ++j) { bP = a[j]*bP + bu[j]; aP *= a[j]; }
        s_pa[slot*9 + dsub] = aP;
        s_pb[slot*9 + dsub] = bP;
        __syncthreads();

        {   // warp `wid` scans the 32 slot-partials of channel dsub==wid
            float ai = s_pa[lane*9 + wid];
            float bi = s_pb[lane*9 + wid];
            #pragma unroll
            for (int off = 1; off < 32; off <<= 1) {
                float pa = __shfl_up_sync(0xffffffffu, ai, off);
                float pb = __shfl_up_sync(0xffffffffu, bi, off);
                if (lane >= off) { bi = ai*pb + bi; ai *= pa; }
            }
            float aE = __shfl_up_sync(0xffffffffu, ai, 1);
            float bE = __shfl_up_sync(0xffffffffu, bi, 1);
            if (lane == 0) { aE = 1.f; bE = 0.f; }
            s_hs[lane*9 + wid] = aE*hprev + bE;
            float aI = __shfl_sync(0xffffffffu, ai, 31);
            float bI = __shfl_sync(0xffffffffu, bi, 31);
            hprev = aI*hprev + bI;
        }
        __syncthreads();

        float h = s_hs[slot*9 + dsub];
        #pragma unroll
        for (int j = 0; j < 8; ++j) {
            h = a[j]*h + bu[j];
            ys_b[(size_t)pos[j]*(KDIR*DI)] = Cv[j]*h + du[j];
        }
    }
}

// =====================================================================
// K5: sequential sum over K + gelu(tanh) + out_proj (f32x2 o-pairs)
// grid (HW/64, B), block 256
// =====================================================================
__global__ void __launch_bounds__(256) k5_out(const float* __restrict__ ow,
                                              float* __restrict__ out) {
    extern __shared__ float sm5[];
    float* sw = sm5;              // transposed: sw[d*98 + o]
    float* sg = sm5 + DI*98;      // sg[d*68 + t]
    int b = blockIdx.y, pos0 = blockIdx.x * 64, tid = threadIdx.x;

    for (int i = tid; i < CIN*DI; i += 256) {
        int o = i / DI, d = i % DI;
        sw[d*98 + o] = ow[i];
    }
    // phase 1: sequential reads, sum over k, gelu
    int lane = tid & 31, wid = tid >> 5;
    #pragma unroll
    for (int pp = 0; pp < 8; ++pp) {
        int po = wid*8 + pp;
        const float* src = &g_ys[((size_t)b*HWSZ + pos0 + po)*(KDIR*DI)];
        float acc[6] = {0,0,0,0,0,0};
        #pragma unroll
        for (int kk = 0; kk < KDIR; ++kk)
            #pragma unroll
            for (int i = 0; i < 6; ++i) acc[i] += src[kk*DI + lane + 32*i];
        #pragma unroll
        for (int i = 0; i < 6; ++i) {
            float v = acc[i];
            float z = 0.7978845608f * (v + 0.044715f*v*v*v);
            float t = 2.f / (1.f + __expf(-2.f*z)) - 1.f;
            sg[(lane + 32*i)*68 + po] = 0.5f * v * (1.f + t);
        }
    }
    __syncthreads();

    // phase 2: out[o] = sum_d w[o,d]*g[d], f32x2 over o-pairs
    int tg = tid & 15, og = tid >> 4;
    int t0 = tg*4, o0 = og*6;
    unsigned long long acc2[3][4];
    #pragma unroll
    for (int i = 0; i < 3; i++)
        #pragma unroll
        for (int j = 0; j < 4; j++) acc2[i][j] = 0ull;

    for (int d = 0; d < DI; ++d) {
        float4 gv = *(const float4*)&sg[d*68 + t0];
        unsigned long long gp[4] = {pk2(gv.x, gv.x), pk2(gv.y, gv.y),
                                    pk2(gv.z, gv.z), pk2(gv.w, gv.w)};
        const float* wrow = &sw[d*98 + o0];
        #pragma unroll
        for (int i = 0; i < 3; ++i) {
            unsigned long long wp = *(const unsigned long long*)&wrow[2*i];
            #pragma unroll
            for (int t = 0; t < 4; ++t) FMA2(acc2[i][t], wp, gp[t]);
        }
    }
    #pragma unroll
    for (int i = 0; i < 3; ++i) {
        float lo[4], hi[4];
        #pragma unroll
        for (int t = 0; t < 4; ++t) upk2(lo[t], hi[t], acc2[i][t]);
        size_t r0 = ((size_t)b*CIN + o0 + 2*i)*HWSZ + pos0 + t0;
        *(float4*)&out[r0]        = make_float4(lo[0], lo[1], lo[2], lo[3]);
        *(float4*)&out[r0 + HWSZ] = make_float4(hi[0], hi[1], hi[2], hi[3]);
    }
}

// =====================================================================
extern "C" void kernel_launch(void* const* d_in, const int* in_sizes, int n_in,
                              void* d_out, int out_size) {
    const float* x    = (const float*)d_in[0];
    const int*   scan = (const int*)d_in[1];
    // d_in[2] = inverse_ids (unused now)
    const float* ipw  = (const float*)d_in[3];
    const float* cw   = (const float*)d_in[4];
    const float* cb   = (const float*)d_in[5];
    const float* xpw  = (const float*)d_in[6];
    const float* dtw  = (const float*)d_in[7];
    const float* dtb  = (const float*)d_in[8];
    const float* Alog = (const float*)d_in[9];
    const float* Dsv  = (const float*)d_in[10];
    const float* ow   = (const float*)d_in[11];
    float* out = (float*)d_out;

    const int SM1 = (96*194 + 96*68) * 4;
    const int SM3 = (DI*68 + DI*33) * 4;
    const int SM5 = (DI*98 + DI*68) * 4;
    cudaFuncSetAttribute(k1_inproj,  cudaFuncAttributeMaxDynamicSharedMemorySize, SM1);
    cudaFuncSetAttribute(k3_proj_tr, cudaFuncAttributeMaxDynamicSharedMemorySize, SM3);
    cudaFuncSetAttribute(k5_out,     cudaFuncAttributeMaxDynamicSharedMemorySize, SM5);

    dim3 g1(HWSZ/64, BATCH);
    k1_inproj<<<g1, 256, SM1>>>(x, ipw);
    dim3 g2(HH/8, DI, BATCH);
    k2_conv<<<g2, 256>>>(cw, cb);
    dim3 g3(HWSZ/64, BATCH);
    k3_proj_tr<<<g3, 256, SM3>>>(xpw);
    dim3 g4(DI/8, KDIR, BATCH);
    k4_scan<<<g4, 256>>>(dtw, dtb, Alog, Dsv, scan);
    dim3 g5(HWSZ/64, BATCH);
    k5_out<<<g5, 256, SM5>>>(ow, out);
}